// round 2
// baseline (speedup 1.0000x reference)
#include <cuda_runtime.h>

#ifndef EPSF
#define EPSF 1e-07f
#endif

#define NTHREADS 256
#define UNROLL   8
#define MAXBLK   8192

static __device__ float        g_partials[MAXBLK];
static __device__ unsigned int g_count;   // zero at load; self-resets each launch

__device__ __forceinline__ float ciou_term(float4 p, float4 t) {
    float px1 = p.x, py1 = p.y, px2 = p.z, py2 = p.w;
    float tx1 = t.x, ty1 = t.y, tx2 = t.z, ty2 = t.w;

    float iw = fmaxf(fminf(px2, tx2) - fmaxf(px1, tx1), 0.0f);
    float ih = fmaxf(fminf(py2, ty2) - fmaxf(py1, ty1), 0.0f);
    float inter = iw * ih;

    float pw = px2 - px1, ph = py2 - py1;
    float tw = tx2 - tx1, th = ty2 - ty1;
    float iou = inter / (pw * ph + tw * th - inter + EPSF);

    float dcx = 0.5f * (px1 + px2) - 0.5f * (tx1 + tx2);
    float dcy = 0.5f * (py1 + py2) - 0.5f * (ty1 + ty2);
    float center_dist_sq = dcx * dcx + dcy * dcy;

    float cw = fmaxf(px2, tx2) - fminf(px1, tx1);
    float ch = fmaxf(py2, ty2) - fminf(py1, ty1);
    float c_diag_sq = cw * cw + ch * ch + EPSF;           // eps inside bbox_iou
    float center_term = center_dist_sq / (c_diag_sq + EPSF); // eps again in forward()

    float sw = (pw - tw) / (tw + EPSF);
    float sh = (ph - th) / (th + EPSF);

    return (1.0f - iou) + 2.0f * center_term + (sw * sw + sh * sh);
}

__global__ void __launch_bounds__(NTHREADS)
ciou_fused_kernel(const float4* __restrict__ pred,
                  const float4* __restrict__ targ,
                  float* __restrict__ out,
                  int n) {
    const int stride = gridDim.x * NTHREADS;
    const int base   = blockIdx.x * NTHREADS + threadIdx.x;

    float local = 0.0f;

    if (base + (UNROLL - 1) * stride < n) {
        // fast path: all UNROLL elements in range — front-batch all loads
        float4 P[UNROLL], T[UNROLL];
        #pragma unroll
        for (int k = 0; k < UNROLL; k++) {
            P[k] = pred[base + k * stride];
            T[k] = targ[base + k * stride];
        }
        #pragma unroll
        for (int k = 0; k < UNROLL; k++)
            local += ciou_term(P[k], T[k]);
        // residual beyond the tiled region (normally none)
        for (int i = base + UNROLL * stride; i < n; i += stride)
            local += ciou_term(pred[i], targ[i]);
    } else {
        for (int i = base; i < n; i += stride)
            local += ciou_term(pred[i], targ[i]);
    }

    // intra-block reduce
    #pragma unroll
    for (int off = 16; off > 0; off >>= 1)
        local += __shfl_down_sync(0xFFFFFFFFu, local, off);

    __shared__ float warp_sums[NTHREADS / 32];
    int lane = threadIdx.x & 31;
    int wid  = threadIdx.x >> 5;
    if (lane == 0) warp_sums[wid] = local;
    __syncthreads();

    __shared__ bool amLast;
    if (threadIdx.x == 0) {
        float bsum = 0.0f;
        #pragma unroll
        for (int w = 0; w < NTHREADS / 32; w++) bsum += warp_sums[w];
        g_partials[blockIdx.x] = bsum;
        __threadfence();
        // atomicInc wraps to 0 at gridDim.x-1 → counter self-resets for next replay
        unsigned int pos = atomicInc(&g_count, gridDim.x - 1);
        amLast = (pos == gridDim.x - 1);
    }
    __syncthreads();

    if (amLast) {
        // last block: sum all partials in double
        double v = 0.0;
        for (int i = threadIdx.x; i < gridDim.x; i += NTHREADS)
            v += (double)g_partials[i];
        #pragma unroll
        for (int off = 16; off > 0; off >>= 1)
            v += __shfl_down_sync(0xFFFFFFFFu, v, off);

        __shared__ double dsums[NTHREADS / 32];
        if (lane == 0) dsums[wid] = v;
        __syncthreads();
        if (threadIdx.x == 0) {
            double tot = 0.0;
            #pragma unroll
            for (int w = 0; w < NTHREADS / 32; w++) tot += dsums[w];
            out[0] = (float)(tot / (double)n);
        }
    }
}

extern "C" void kernel_launch(void* const* d_in, const int* in_sizes, int n_in,
                              void* d_out, int out_size) {
    const float4* pred = (const float4*)d_in[0];
    const float4* targ = (const float4*)d_in[1];
    int n = in_sizes[0] / 4;   // floats -> boxes

    int blocks = (n + NTHREADS * UNROLL - 1) / (NTHREADS * UNROLL);
    if (blocks > MAXBLK) blocks = MAXBLK;
    if (blocks < 1) blocks = 1;

    ciou_fused_kernel<<<blocks, NTHREADS>>>(pred, targ, (float*)d_out, n);
}

// round 3
// speedup vs baseline: 1.3015x; 1.3015x over previous
#include <cuda_runtime.h>

#ifndef EPSF
#define EPSF 1e-07f
#endif

#define NTHREADS 256
#define UNROLL   4
#define MAXBLK   8192

static __device__ float        g_partials[MAXBLK];
static __device__ unsigned int g_count;   // zero at load; atomicInc wrap self-resets

__device__ __forceinline__ float ciou_term(float4 p, float4 t) {
    float px1 = p.x, py1 = p.y, px2 = p.z, py2 = p.w;
    float tx1 = t.x, ty1 = t.y, tx2 = t.z, ty2 = t.w;

    float iw = fmaxf(fminf(px2, tx2) - fmaxf(px1, tx1), 0.0f);
    float ih = fmaxf(fminf(py2, ty2) - fmaxf(py1, ty1), 0.0f);
    float inter = iw * ih;

    float pw = px2 - px1, ph = py2 - py1;
    float tw = tx2 - tx1, th = ty2 - ty1;
    float iou = inter / (pw * ph + tw * th - inter + EPSF);

    float dcx = 0.5f * (px1 + px2) - 0.5f * (tx1 + tx2);
    float dcy = 0.5f * (py1 + py2) - 0.5f * (ty1 + ty2);
    float center_dist_sq = dcx * dcx + dcy * dcy;

    float cw = fmaxf(px2, tx2) - fminf(px1, tx1);
    float ch = fmaxf(py2, ty2) - fminf(py1, ty1);
    float c_diag_sq = cw * cw + ch * ch + EPSF;               // eps inside bbox_iou
    float center_term = center_dist_sq / (c_diag_sq + EPSF);  // eps again in forward()

    float sw = (pw - tw) / (tw + EPSF);
    float sh = (ph - th) / (th + EPSF);

    return (1.0f - iou) + 2.0f * center_term + (sw * sw + sh * sh);
}

__global__ void __launch_bounds__(NTHREADS, 4)
ciou_fused_kernel(const float4* __restrict__ pred,
                  const float4* __restrict__ targ,
                  float* __restrict__ out,
                  int n) {
    const int stride = gridDim.x * NTHREADS;
    const int base   = blockIdx.x * NTHREADS + threadIdx.x;

    float local = 0.0f;

    if (base + (UNROLL - 1) * stride < n) {
        float4 P[UNROLL], T[UNROLL];
        #pragma unroll
        for (int k = 0; k < UNROLL; k++) {
            P[k] = __ldcs(&pred[base + k * stride]);
            T[k] = __ldcs(&targ[base + k * stride]);
        }
        #pragma unroll
        for (int k = 0; k < UNROLL; k++)
            local += ciou_term(P[k], T[k]);
        for (int i = base + UNROLL * stride; i < n; i += stride)
            local += ciou_term(__ldcs(&pred[i]), __ldcs(&targ[i]));
    } else {
        for (int i = base; i < n; i += stride)
            local += ciou_term(__ldcs(&pred[i]), __ldcs(&targ[i]));
    }

    // intra-block reduce
    #pragma unroll
    for (int off = 16; off > 0; off >>= 1)
        local += __shfl_down_sync(0xFFFFFFFFu, local, off);

    __shared__ float warp_sums[NTHREADS / 32];
    int lane = threadIdx.x & 31;
    int wid  = threadIdx.x >> 5;
    if (lane == 0) warp_sums[wid] = local;
    __syncthreads();

    __shared__ bool amLast;
    if (threadIdx.x == 0) {
        float bsum = 0.0f;
        #pragma unroll
        for (int w = 0; w < NTHREADS / 32; w++) bsum += warp_sums[w];
        g_partials[blockIdx.x] = bsum;
        __threadfence();
        unsigned int pos = atomicInc(&g_count, gridDim.x - 1);
        amLast = (pos == gridDim.x - 1);
    }
    __syncthreads();

    if (amLast) {
        double v = 0.0;
        for (int i = threadIdx.x; i < gridDim.x; i += NTHREADS)
            v += (double)g_partials[i];
        #pragma unroll
        for (int off = 16; off > 0; off >>= 1)
            v += __shfl_down_sync(0xFFFFFFFFu, v, off);

        __shared__ double dsums[NTHREADS / 32];
        if (lane == 0) dsums[wid] = v;
        __syncthreads();
        if (threadIdx.x == 0) {
            double tot = 0.0;
            #pragma unroll
            for (int w = 0; w < NTHREADS / 32; w++) tot += dsums[w];
            out[0] = (float)(tot / (double)n);
        }
    }
}

extern "C" void kernel_launch(void* const* d_in, const int* in_sizes, int n_in,
                              void* d_out, int out_size) {
    const float4* pred = (const float4*)d_in[0];
    const float4* targ = (const float4*)d_in[1];
    int n = in_sizes[0] / 4;   // floats -> boxes

    int blocks = (n + NTHREADS * UNROLL - 1) / (NTHREADS * UNROLL);
    if (blocks > MAXBLK) blocks = MAXBLK;
    if (blocks < 1) blocks = 1;

    ciou_fused_kernel<<<blocks, NTHREADS>>>(pred, targ, (float*)d_out, n);
}